// round 11
// baseline (speedup 1.0000x reference)
#include <cuda_runtime.h>
#include <cuda_fp16.h>
#include <cstdint>

#define NV 200000
#define KK 27
#define CC 64
#define BM 128
#define NT 256
#define NWARP 8
#define STAGES 2
#define BN_EPS 1e-5f
#define PREP_GRID 512

#define A_BYTES (BM * 128)
#define B_BYTES (CC * 128)
#define STAGE_BYTES (A_BYTES + B_BYTES)            // 24576
#define SMEM_CONV (STAGES * STAGE_BYTES)           // 49152
#define SMEM_CONV2 (SMEM_CONV + 512)               // + scale/shift float4[32]

#define SW(o) ((o) ^ (((o) >> 3) & 0x70))

// ---------------- device scratch ----------------
__device__ alignas(256) __half g_y[(size_t)NV * CC];
__device__ alignas(256) __half g_t16[(size_t)NV * CC];
__device__ alignas(256) __half g_Wh[2][KK * CC * CC];
__device__ float g_sum[2][CC];
__device__ float g_sumsq[2][CC];
__device__ unsigned g_arrive;
__device__ int g_is64;

// ---------------- helpers ----------------
__device__ __forceinline__ uint32_t smem_u32(const void* p) {
    return (uint32_t)__cvta_generic_to_shared(p);
}
__device__ __forceinline__ void cp16(uint32_t dst, const void* src) {
    asm volatile("cp.async.cg.shared.global [%0], [%1], 16;\n" :: "r"(dst), "l"(src));
}
__device__ __forceinline__ int ld_idx(const void* nbr, bool is64, int gn, int k) {
    size_t pos = (size_t)gn * KK + k;
    return is64 ? (int)((const long long*)nbr)[pos] : ((const int*)nbr)[pos];
}

// ---------------- zero stats/counter + detect index dtype ----------------
__global__ void k_zero(const void* __restrict__ nbr) {
    int t = threadIdx.x;
    if (t < CC) {
        g_sum[0][t] = 0.f; g_sum[1][t] = 0.f;
        g_sumsq[0][t] = 0.f; g_sumsq[1][t] = 0.f;
    }
    if (t == 0) {
        g_arrive = 0u;
        const long long* p = (const long long*)nbr;
        int ok = 1;
        for (int i = 0; i < 64; ++i) {
            long long v = p[i];
            if (v < 0 || v >= NV) { ok = 0; break; }
        }
        g_is64 = ok;
    }
}

// ---------------- wcvt + stats0 + gridsync + bnrelu0, one kernel ----------------
__global__ void k_prep(const float* __restrict__ x,
                       const float* __restrict__ W1,
                       const float* __restrict__ W2,
                       const float* __restrict__ gamma1,
                       const float* __restrict__ beta1) {
    // phase A1: weight convert (pre-swizzled)
    const int wtotal = KK * CC * CC;
    for (int i = blockIdx.x * blockDim.x + threadIdx.x; i < wtotal;
         i += gridDim.x * blockDim.x) {
        int k  = i >> 12;
        int ci = (i & 4095) >> 6;
        int co = i & 63;
        uint32_t off = (uint32_t)SW(ci * 128 + co * 2) >> 1;
        g_Wh[0][k * 4096 + off] = __float2half_rn(W1[i]);
        g_Wh[1][k * 4096 + off] = __float2half_rn(W2[i]);
    }
    // phase A2: column stats over x
    __shared__ float sh[2][4][CC];
    {
        int ch = threadIdx.x & 63;
        int rg = threadIdx.x >> 6;
        float s = 0.f, s2 = 0.f;
        for (int row = blockIdx.x * 4 + rg; row < NV; row += gridDim.x * 4) {
            float v = x[(size_t)row * CC + ch];
            s += v; s2 += v * v;
        }
        sh[0][rg][ch] = s; sh[1][rg][ch] = s2;
        __syncthreads();
        if (rg == 0) {
            s  = sh[0][0][ch] + sh[0][1][ch] + sh[0][2][ch] + sh[0][3][ch];
            s2 = sh[1][0][ch] + sh[1][1][ch] + sh[1][2][ch] + sh[1][3][ch];
            atomicAdd(&g_sum[0][ch], s);
            atomicAdd(&g_sumsq[0][ch], s2);
        }
    }
    // grid-wide sync (all PREP_GRID CTAs resident)
    __threadfence();
    __syncthreads();
    if (threadIdx.x == 0) {
        atomicAdd(&g_arrive, 1u);
        while (atomicAdd(&g_arrive, 0u) < (unsigned)gridDim.x) {}
    }
    __syncthreads();
    // phase B: finalize + BN + ReLU + fp16 quantize into g_y
    __shared__ float s_scale[CC], s_shift[CC];
    if (threadIdx.x < CC) {
        int c = threadIdx.x;
        float mean = g_sum[0][c] / (float)NV;
        float var  = g_sumsq[0][c] / (float)NV - mean * mean;
        float s = gamma1[c] * rsqrtf(var + BN_EPS);
        s_scale[c] = s;
        s_shift[c] = beta1[c] - mean * s;
    }
    __syncthreads();
    const int total = NV * CC / 8;
    for (int i = blockIdx.x * blockDim.x + threadIdx.x; i < total;
         i += gridDim.x * blockDim.x) {
        int cb = (i & 7) << 3;
        float4 u0 = ((const float4*)x)[2 * i];
        float4 u1 = ((const float4*)x)[2 * i + 1];
        float f[8] = {u0.x, u0.y, u0.z, u0.w, u1.x, u1.y, u1.z, u1.w};
        #pragma unroll
        for (int j = 0; j < 8; ++j)
            f[j] = fmaxf(fmaf(f[j], s_scale[cb + j], s_shift[cb + j]), 0.f);
        uint4 o;
        *(__half2*)&o.x = __floats2half2_rn(f[0], f[1]);
        *(__half2*)&o.y = __floats2half2_rn(f[2], f[3]);
        *(__half2*)&o.z = __floats2half2_rn(f[4], f[5]);
        *(__half2*)&o.w = __floats2half2_rn(f[6], f[7]);
        ((uint4*)g_y)[i] = o;
    }
}

// ---------------- conv1: gather(g_y) GEMM -> g_t16 + fused stats ----------------
__global__ void __launch_bounds__(NT, 4)
k_conv1(const void* __restrict__ nbr)
{
    extern __shared__ char smem[];
    const uint32_t sb = smem_u32(smem);
    const __half* __restrict__ Wh = g_Wh[0];

    const int tid = threadIdx.x;
    const int warp = tid >> 5, lane = tid & 31;
    const int wm = warp >> 1, wn = warp & 1;
    const int m0 = blockIdx.x * BM;
    const bool is64 = (g_is64 != 0);

    float acc[2][4][4];
    #pragma unroll
    for (int a = 0; a < 2; ++a)
        #pragma unroll
        for (int b = 0; b < 4; ++b)
            #pragma unroll
            for (int c = 0; c < 4; ++c) acc[a][b][c] = 0.f;

    const int r  = tid >> 1;
    const int hs = tid & 1;
    const int gn = (m0 + r < NV) ? (m0 + r) : 0;

    auto fill = [&](int st, int gi, int k) {
        const __half* srcA = g_y + (size_t)gi * CC + hs * 32;
        uint32_t abase = sb + st * STAGE_BYTES;
        #pragma unroll
        for (int j = 0; j < 4; ++j) {
            uint32_t boff = (uint32_t)(r * 128 + (hs * 4 + j) * 16);
            cp16(abase + SW(boff), srcA + j * 8);
        }
        const __half* srcB = Wh + k * 4096;
        uint32_t bbase = abase + A_BYTES;
        cp16(bbase + tid * 16,        srcB + tid * 8);
        cp16(bbase + (tid + NT) * 16, srcB + (tid + NT) * 8);
    };

    {
        int i0 = ld_idx(nbr, is64, gn, 0);
        int i1 = ld_idx(nbr, is64, gn, 1);
        fill(0, i0, 0);
        asm volatile("cp.async.commit_group;\n");
        fill(1, i1, 1);
        asm volatile("cp.async.commit_group;\n");
    }
    int gi_next = ld_idx(nbr, is64, gn, 2);

    for (int k = 0; k < KK; ++k) {
        const int st = k & 1;
        if (k + 1 < KK)
            asm volatile("cp.async.wait_group 1;\n");
        else
            asm volatile("cp.async.wait_group 0;\n");
        __syncthreads();

        const uint32_t abase = sb + st * STAGE_BYTES;
        const uint32_t bbase = abase + A_BYTES;

        #pragma unroll
        for (int ks = 0; ks < 4; ++ks) {
            const int k0 = ks * 16;
            uint32_t a0[4], a1[4], b0[4], b1[4];
            {
                int row = wm * 32 + (lane & 15);
                int col = k0 + (lane >> 4) * 8;
                uint32_t ad = abase + SW((uint32_t)(row * 128 + col * 2));
                asm volatile("ldmatrix.sync.aligned.m8n8.x4.shared.b16 {%0,%1,%2,%3}, [%4];"
                             : "=r"(a0[0]), "=r"(a0[1]), "=r"(a0[2]), "=r"(a0[3]) : "r"(ad));
                ad = abase + SW((uint32_t)((row + 16) * 128 + col * 2));
                asm volatile("ldmatrix.sync.aligned.m8n8.x4.shared.b16 {%0,%1,%2,%3}, [%4];"
                             : "=r"(a1[0]), "=r"(a1[1]), "=r"(a1[2]), "=r"(a1[3]) : "r"(ad));
            }
            {
                int krow = k0 + ((lane >> 3) & 1) * 8 + (lane & 7);
                int coll = wn * 32 + (lane >> 4) * 8;
                uint32_t ad = bbase + SW((uint32_t)(krow * 128 + coll * 2));
                asm volatile("ldmatrix.sync.aligned.m8n8.x4.trans.shared.b16 {%0,%1,%2,%3}, [%4];"
                             : "=r"(b0[0]), "=r"(b0[1]), "=r"(b0[2]), "=r"(b0[3]) : "r"(ad));
                ad = bbase + SW((uint32_t)(krow * 128 + (coll + 16) * 2));
                asm volatile("ldmatrix.sync.aligned.m8n8.x4.trans.shared.b16 {%0,%1,%2,%3}, [%4];"
                             : "=r"(b1[0]), "=r"(b1[1]), "=r"(b1[2]), "=r"(b1[3]) : "r"(ad));
            }
            #pragma unroll
            for (int mt = 0; mt < 2; ++mt) {
                const uint32_t* A = mt ? a1 : a0;
                #pragma unroll
                for (int nt = 0; nt < 4; ++nt) {
                    const uint32_t* B = (nt < 2) ? b0 : b1;
                    uint32_t bb0 = B[(nt & 1) * 2], bb1 = B[(nt & 1) * 2 + 1];
                    float* C = acc[mt][nt];
                    asm volatile(
                        "mma.sync.aligned.m16n8k16.row.col.f32.f16.f16.f32 "
                        "{%0,%1,%2,%3}, {%4,%5,%6,%7}, {%8,%9}, {%0,%1,%2,%3};"
                        : "+f"(C[0]), "+f"(C[1]), "+f"(C[2]), "+f"(C[3])
                        : "r"(A[0]), "r"(A[1]), "r"(A[2]), "r"(A[3]),
                          "r"(bb0), "r"(bb1));
                }
            }
        }

        if (k + 2 < KK) {
            __syncthreads();
            fill(st, gi_next, k + 2);
            asm volatile("cp.async.commit_group;\n");
            gi_next = ld_idx(nbr, is64, gn, (k + 3 < KK) ? (k + 3) : (KK - 1));
        }
    }

    // epilogue: write fp16 + fused stats (stage 1)
    float ls[8], lq[8];
    #pragma unroll
    for (int j = 0; j < 8; ++j) { ls[j] = 0.f; lq[j] = 0.f; }

    #pragma unroll
    for (int mt = 0; mt < 2; ++mt) {
        int rbase = m0 + wm * 32 + mt * 16 + (lane >> 2);
        bool v0 = rbase < NV, v1 = rbase + 8 < NV;
        #pragma unroll
        for (int nt = 0; nt < 4; ++nt) {
            int col = wn * 32 + nt * 8 + (lane & 3) * 2;
            float* C = acc[mt][nt];
            if (v0) {
                size_t o = (size_t)rbase * CC + col;
                *(__half2*)(g_t16 + o) = __floats2half2_rn(C[0], C[1]);
                ls[nt * 2]     += C[0]; lq[nt * 2]     += C[0] * C[0];
                ls[nt * 2 + 1] += C[1]; lq[nt * 2 + 1] += C[1] * C[1];
            }
            if (v1) {
                size_t o = (size_t)(rbase + 8) * CC + col;
                *(__half2*)(g_t16 + o) = __floats2half2_rn(C[2], C[3]);
                ls[nt * 2]     += C[2]; lq[nt * 2]     += C[2] * C[2];
                ls[nt * 2 + 1] += C[3]; lq[nt * 2 + 1] += C[3] * C[3];
            }
        }
    }
    #pragma unroll
    for (int m = 4; m <= 16; m <<= 1) {
        #pragma unroll
        for (int j = 0; j < 8; ++j) {
            ls[j] += __shfl_xor_sync(0xffffffffu, ls[j], m);
            lq[j] += __shfl_xor_sync(0xffffffffu, lq[j], m);
        }
    }
    float* red = (float*)smem;
    __syncthreads();
    if ((lane >> 2) == 0) {
        #pragma unroll
        for (int j = 0; j < 8; ++j) {
            int cl = (j >> 1) * 8 + (lane & 3) * 2 + (j & 1);
            red[warp * 32 + cl]              = ls[j];
            red[NWARP * 32 + warp * 32 + cl] = lq[j];
        }
    }
    __syncthreads();
    if (tid < 128) {
        int part = tid >> 6, c = tid & 63;
        int cwn = c >> 5, cl = c & 31;
        const float* base = red + part * NWARP * 32;
        float v = 0.f;
        #pragma unroll
        for (int i = 0; i < 4; ++i) v += base[(2 * i + cwn) * 32 + cl];
        atomicAdd(part ? &g_sumsq[1][c] : &g_sum[1][c], v);
    }
}

// ---------------- conv2: BN2+ReLU on-the-fly gather(g_t16) GEMM + residual ----------------
__global__ void __launch_bounds__(NT, 4)
k_conv2(const void* __restrict__ nbr,
        const float* __restrict__ residual, float* __restrict__ dout,
        const float* __restrict__ gamma2, const float* __restrict__ beta2)
{
    extern __shared__ char smem[];
    const uint32_t sb = smem_u32(smem);
    float4* s4 = (float4*)(smem + SMEM_CONV);   // [32]: (s0,s1,t0,t1) per channel pair
    const __half* __restrict__ Wh = g_Wh[1];

    const int tid = threadIdx.x;
    const int warp = tid >> 5, lane = tid & 31;
    const int wm = warp >> 1, wn = warp & 1;
    const int m0 = blockIdx.x * BM;
    const bool is64 = (g_is64 != 0);

    // prologue: per-CTA BN2 scale/shift
    if (tid < 32) {
        int c0 = tid * 2;
        float m0f = g_sum[1][c0] / (float)NV;
        float v0  = g_sumsq[1][c0] / (float)NV - m0f * m0f;
        float sc0 = gamma2[c0] * rsqrtf(v0 + BN_EPS);
        float sh0 = beta2[c0] - m0f * sc0;
        int c1 = c0 + 1;
        float m1f = g_sum[1][c1] / (float)NV;
        float v1  = g_sumsq[1][c1] / (float)NV - m1f * m1f;
        float sc1 = gamma2[c1] * rsqrtf(v1 + BN_EPS);
        float sh1 = beta2[c1] - m1f * sc1;
        s4[tid] = make_float4(sc0, sc1, sh0, sh1);
    }
    __syncthreads();

    float acc[2][4][4];
    #pragma unroll
    for (int a = 0; a < 2; ++a)
        #pragma unroll
        for (int b = 0; b < 4; ++b)
            #pragma unroll
            for (int c = 0; c < 4; ++c) acc[a][b][c] = 0.f;

    const int r  = tid >> 1;
    const int hs = tid & 1;
    const int gn = (m0 + r < NV) ? (m0 + r) : 0;

    // fill: A via LDG + BN/ReLU transform + STS ; B via cp.async
    auto fill = [&](int st, int gi, int k) {
        const __half* srcA = g_t16 + (size_t)gi * CC + hs * 32;
        char* abase = smem + st * STAGE_BYTES;
        #pragma unroll
        for (int j = 0; j < 4; ++j) {
            uint4 v = *(const uint4*)(srcA + j * 8);
            uint32_t* vi = &v.x;
            uint4 o;
            uint32_t* oi = &o.x;
            #pragma unroll
            for (int p = 0; p < 4; ++p) {
                float4 c4 = s4[hs * 16 + j * 4 + p];
                float2 f = __half22float2(*(__half2*)&vi[p]);
                f.x = fmaxf(fmaf(f.x, c4.x, c4.z), 0.f);
                f.y = fmaxf(fmaf(f.y, c4.y, c4.w), 0.f);
                *(__half2*)&oi[p] = __float22half2_rn(f);
            }
            *(uint4*)(abase + SW((uint32_t)(r * 128 + (hs * 4 + j) * 16))) = o;
        }
        const __half* srcB = Wh + k * 4096;
        uint32_t bbase = sb + st * STAGE_BYTES + A_BYTES;
        cp16(bbase + tid * 16,        srcB + tid * 8);
        cp16(bbase + (tid + NT) * 16, srcB + (tid + NT) * 8);
    };

    {
        int i0 = ld_idx(nbr, is64, gn, 0);
        int i1 = ld_idx(nbr, is64, gn, 1);
        fill(0, i0, 0);
        asm volatile("cp.async.commit_group;\n");
        fill(1, i1, 1);
        asm volatile("cp.async.commit_group;\n");
    }
    int gi_next = ld_idx(nbr, is64, gn, 2);

    for (int k = 0; k < KK; ++k) {
        const int st = k & 1;
        if (k + 1 < KK)
            asm volatile("cp.async.wait_group 1;\n");
        else
            asm volatile("cp.async.wait_group 0;\n");
        __syncthreads();

        const uint32_t abase = sb + st * STAGE_BYTES;
        const uint32_t bbase = abase + A_BYTES;

        #pragma unroll
        for (int ks = 0; ks < 4; ++ks) {
            const int k0 = ks * 16;
            uint32_t a0[4], a1[4], b0[4], b1[4];
            {
                int row = wm * 32 + (lane & 15);
                int col = k0 + (lane >> 4) * 8;
                uint32_t ad = abase + SW((uint32_t)(row * 128 + col * 2));
                asm volatile("ldmatrix.sync.aligned.m8n8.x4.shared.b16 {%0,%1,%2,%3}, [%4];"
                             : "=r"(a0[0]), "=r"(a0[1]), "=r"(a0[2]), "=r"(a0[3]) : "r"(ad));
                ad = abase + SW((uint32_t)((row + 16) * 128 + col * 2));
                asm volatile("ldmatrix.sync.aligned.m8n8.x4.shared.b16 {%0,%1,%2,%3}, [%4];"
                             : "=r"(a1[0]), "=r"(a1[1]), "=r"(a1[2]), "=r"(a1[3]) : "r"(ad));
            }
            {
                int krow = k0 + ((lane >> 3) & 1) * 8 + (lane & 7);
                int coll = wn * 32 + (lane >> 4) * 8;
                uint32_t ad = bbase + SW((uint32_t)(krow * 128 + coll * 2));
                asm volatile("ldmatrix.sync.aligned.m8n8.x4.trans.shared.b16 {%0,%1,%2,%3}, [%4];"
                             : "=r"(b0[0]), "=r"(b0[1]), "=r"(b0[2]), "=r"(b0[3]) : "r"(ad));
                ad = bbase + SW((uint32_t)(krow * 128 + (coll + 16) * 2));
                asm volatile("ldmatrix.sync.aligned.m8n8.x4.trans.shared.b16 {%0,%1,%2,%3}, [%4];"
                             : "=r"(b1[0]), "=r"(b1[1]), "=r"(b1[2]), "=r"(b1[3]) : "r"(ad));
            }
            #pragma unroll
            for (int mt = 0; mt < 2; ++mt) {
                const uint32_t* A = mt ? a1 : a0;
                #pragma unroll
                for (int nt = 0; nt < 4; ++nt) {
                    const uint32_t* B = (nt < 2) ? b0 : b1;
                    uint32_t bb0 = B[(nt & 1) * 2], bb1 = B[(nt & 1) * 2 + 1];
                    float* C = acc[mt][nt];
                    asm volatile(
                        "mma.sync.aligned.m16n8k16.row.col.f32.f16.f16.f32 "
                        "{%0,%1,%2,%3}, {%4,%5,%6,%7}, {%8,%9}, {%0,%1,%2,%3};"
                        : "+f"(C[0]), "+f"(C[1]), "+f"(C[2]), "+f"(C[3])
                        : "r"(A[0]), "r"(A[1]), "r"(A[2]), "r"(A[3]),
                          "r"(bb0), "r"(bb1));
                }
            }
        }

        if (k + 2 < KK) {
            __syncthreads();
            fill(st, gi_next, k + 2);
            asm volatile("cp.async.commit_group;\n");
            gi_next = ld_idx(nbr, is64, gn, (k + 3 < KK) ? (k + 3) : (KK - 1));
        }
    }

    // epilogue: fp32 out + residual (8B vectors)
    #pragma unroll
    for (int mt = 0; mt < 2; ++mt) {
        int rbase = m0 + wm * 32 + mt * 16 + (lane >> 2);
        #pragma unroll
        for (int nt = 0; nt < 4; ++nt) {
            int col = wn * 32 + nt * 8 + (lane & 3) * 2;
            float* C = acc[mt][nt];
            if (rbase < NV) {
                size_t o = (size_t)rbase * CC + col;
                float2 rv = *(const float2*)(residual + o);
                float2 v; v.x = C[0] + rv.x; v.y = C[1] + rv.y;
                *(float2*)(dout + o) = v;
            }
            if (rbase + 8 < NV) {
                size_t o = (size_t)(rbase + 8) * CC + col;
                float2 rv = *(const float2*)(residual + o);
                float2 v; v.x = C[2] + rv.x; v.y = C[3] + rv.y;
                *(float2*)(dout + o) = v;
            }
        }
    }
}

// ---------------- launch ----------------
extern "C" void kernel_launch(void* const* d_in, const int* in_sizes, int n_in,
                              void* d_out, int out_size) {
    const float* x      = (const float*)d_in[0];
    const void*  nbr    = d_in[1];
    const float* W1     = (const float*)d_in[2];
    const float* gamma1 = (const float*)d_in[3];
    const float* beta1  = (const float*)d_in[4];
    const float* W2     = (const float*)d_in[5];
    const float* gamma2 = (const float*)d_in[6];
    const float* beta2  = (const float*)d_in[7];
    float* out = (float*)d_out;

    const int conv_grid = (NV + BM - 1) / BM;

    static int attr_set = 0;
    if (!attr_set) {
        cudaFuncSetAttribute(k_conv1, cudaFuncAttributeMaxDynamicSharedMemorySize,
                             SMEM_CONV);
        cudaFuncSetAttribute(k_conv2, cudaFuncAttributeMaxDynamicSharedMemorySize,
                             SMEM_CONV2);
        attr_set = 1;
    }

    k_zero<<<1, 64>>>(nbr);                                           // 1
    k_prep<<<PREP_GRID, 256>>>(x, W1, W2, gamma1, beta1);             // 2
    k_conv1<<<conv_grid, NT, SMEM_CONV>>>(nbr);                       // 3
    k_conv2<<<conv_grid, NT, SMEM_CONV2>>>(nbr, x, out, gamma2, beta2); // 4 <- ncu
}

// round 12
// speedup vs baseline: 1.2134x; 1.2134x over previous
#include <cuda_runtime.h>
#include <cuda_fp16.h>
#include <cstdint>

#define NV 200000
#define KK 27
#define CC 64
#define BM 128
#define NT 256
#define NWARP 8
#define STAGES 2
#define BN_EPS 1e-5f
#define PREP_GRID 512

#define A_BYTES (BM * 128)
#define B_BYTES (CC * 128)
#define STAGE_BYTES (A_BYTES + B_BYTES)            // 24576
#define SMEM_CONV (STAGES * STAGE_BYTES)           // 49152 -> 4 CTAs/SM

#define SW(o) ((o) ^ (((o) >> 3) & 0x70))

// ---------------- device scratch ----------------
__device__ alignas(256) __half g_y[(size_t)NV * CC];
__device__ alignas(256) __half g_t16[(size_t)NV * CC];
__device__ alignas(256) __half g_Wh[2][KK * CC * CC];
__device__ float g_sum[2][CC];
__device__ float g_sumsq[2][CC];
__device__ unsigned g_arrive;
__device__ int g_is64;

// ---------------- helpers ----------------
__device__ __forceinline__ uint32_t smem_u32(const void* p) {
    return (uint32_t)__cvta_generic_to_shared(p);
}
__device__ __forceinline__ void cp16(uint32_t dst, const void* src) {
    asm volatile("cp.async.cg.shared.global [%0], [%1], 16;\n" :: "r"(dst), "l"(src));
}
__device__ __forceinline__ int ld_idx(const void* nbr, bool is64, int gn, int k) {
    size_t pos = (size_t)gn * KK + k;
    return is64 ? (int)((const long long*)nbr)[pos] : ((const int*)nbr)[pos];
}

// ---------------- zero stats/counter + detect index dtype ----------------
__global__ void k_zero(const void* __restrict__ nbr) {
    int t = threadIdx.x;
    if (t < CC) {
        g_sum[0][t] = 0.f; g_sum[1][t] = 0.f;
        g_sumsq[0][t] = 0.f; g_sumsq[1][t] = 0.f;
    }
    if (t == 0) {
        g_arrive = 0u;
        const long long* p = (const long long*)nbr;
        int ok = 1;
        for (int i = 0; i < 64; ++i) {
            long long v = p[i];
            if (v < 0 || v >= NV) { ok = 0; break; }
        }
        g_is64 = ok;
    }
}

// ---------------- wcvt + stats0 + gridsync + bnrelu0, one kernel ----------------
__global__ void k_prep(const float* __restrict__ x,
                       const float* __restrict__ W1,
                       const float* __restrict__ W2,
                       const float* __restrict__ gamma1,
                       const float* __restrict__ beta1) {
    const int wtotal = KK * CC * CC;
    for (int i = blockIdx.x * blockDim.x + threadIdx.x; i < wtotal;
         i += gridDim.x * blockDim.x) {
        int k  = i >> 12;
        int ci = (i & 4095) >> 6;
        int co = i & 63;
        uint32_t off = (uint32_t)SW(ci * 128 + co * 2) >> 1;
        g_Wh[0][k * 4096 + off] = __float2half_rn(W1[i]);
        g_Wh[1][k * 4096 + off] = __float2half_rn(W2[i]);
    }
    __shared__ float sh[2][4][CC];
    {
        int ch = threadIdx.x & 63;
        int rg = threadIdx.x >> 6;
        float s = 0.f, s2 = 0.f;
        for (int row = blockIdx.x * 4 + rg; row < NV; row += gridDim.x * 4) {
            float v = x[(size_t)row * CC + ch];
            s += v; s2 += v * v;
        }
        sh[0][rg][ch] = s; sh[1][rg][ch] = s2;
        __syncthreads();
        if (rg == 0) {
            s  = sh[0][0][ch] + sh[0][1][ch] + sh[0][2][ch] + sh[0][3][ch];
            s2 = sh[1][0][ch] + sh[1][1][ch] + sh[1][2][ch] + sh[1][3][ch];
            atomicAdd(&g_sum[0][ch], s);
            atomicAdd(&g_sumsq[0][ch], s2);
        }
    }
    // grid-wide sync (all PREP_GRID CTAs resident)
    __threadfence();
    __syncthreads();
    if (threadIdx.x == 0) {
        atomicAdd(&g_arrive, 1u);
        while (atomicAdd(&g_arrive, 0u) < (unsigned)gridDim.x) {}
    }
    __syncthreads();
    // finalize + BN + ReLU + fp16 quantize into g_y
    __shared__ float s_scale[CC], s_shift[CC];
    if (threadIdx.x < CC) {
        int c = threadIdx.x;
        float mean = g_sum[0][c] / (float)NV;
        float var  = g_sumsq[0][c] / (float)NV - mean * mean;
        float s = gamma1[c] * rsqrtf(var + BN_EPS);
        s_scale[c] = s;
        s_shift[c] = beta1[c] - mean * s;
    }
    __syncthreads();
    const int total = NV * CC / 8;
    for (int i = blockIdx.x * blockDim.x + threadIdx.x; i < total;
         i += gridDim.x * blockDim.x) {
        int cb = (i & 7) << 3;
        float4 u0 = ((const float4*)x)[2 * i];
        float4 u1 = ((const float4*)x)[2 * i + 1];
        float f[8] = {u0.x, u0.y, u0.z, u0.w, u1.x, u1.y, u1.z, u1.w};
        #pragma unroll
        for (int j = 0; j < 8; ++j)
            f[j] = fmaxf(fmaf(f[j], s_scale[cb + j], s_shift[cb + j]), 0.f);
        uint4 o;
        *(__half2*)&o.x = __floats2half2_rn(f[0], f[1]);
        *(__half2*)&o.y = __floats2half2_rn(f[2], f[3]);
        *(__half2*)&o.z = __floats2half2_rn(f[4], f[5]);
        *(__half2*)&o.w = __floats2half2_rn(f[6], f[7]);
        ((uint4*)g_y)[i] = o;
    }
}

// ---------------- bnrelu stage1: g_t16 -> BN2+ReLU -> g_y (fp16) ----------------
__global__ void k_bnrelu1(const float* __restrict__ gamma,
                          const float* __restrict__ beta) {
    __shared__ float s_scale[CC], s_shift[CC];
    if (threadIdx.x < CC) {
        int c = threadIdx.x;
        float mean = g_sum[1][c] / (float)NV;
        float var  = g_sumsq[1][c] / (float)NV - mean * mean;
        float s = gamma[c] * rsqrtf(var + BN_EPS);
        s_scale[c] = s;
        s_shift[c] = beta[c] - mean * s;
    }
    __syncthreads();
    const int total = NV * CC / 8;
    for (int i = blockIdx.x * blockDim.x + threadIdx.x; i < total;
         i += gridDim.x * blockDim.x) {
        int cb = (i & 7) << 3;
        uint4 u = ((const uint4*)g_t16)[i];
        float2 p0 = __half22float2(*(__half2*)&u.x);
        float2 p1 = __half22float2(*(__half2*)&u.y);
        float2 p2 = __half22float2(*(__half2*)&u.z);
        float2 p3 = __half22float2(*(__half2*)&u.w);
        float f[8] = {p0.x, p0.y, p1.x, p1.y, p2.x, p2.y, p3.x, p3.y};
        #pragma unroll
        for (int j = 0; j < 8; ++j)
            f[j] = fmaxf(fmaf(f[j], s_scale[cb + j], s_shift[cb + j]), 0.f);
        uint4 o;
        *(__half2*)&o.x = __floats2half2_rn(f[0], f[1]);
        *(__half2*)&o.y = __floats2half2_rn(f[2], f[3]);
        *(__half2*)&o.z = __floats2half2_rn(f[4], f[5]);
        *(__half2*)&o.w = __floats2half2_rn(f[6], f[7]);
        ((uint4*)g_y)[i] = o;
    }
}

// ---------------- gather-GEMM conv: BM=128, 8 warps (4m x 2n, m32n32), occ 4 ----------------
__global__ void __launch_bounds__(NT, 4)
k_conv(const void* __restrict__ nbr, int which,
       const float* __restrict__ residual, float* __restrict__ dout)
{
    extern __shared__ char smem[];
    const uint32_t sb = smem_u32(smem);
    const __half* __restrict__ Wh = g_Wh[which];

    const int tid = threadIdx.x;
    const int warp = tid >> 5, lane = tid & 31;
    const int wm = warp >> 1, wn = warp & 1;
    const int m0 = blockIdx.x * BM;
    const bool is64 = (g_is64 != 0);

    float acc[2][4][4];
    #pragma unroll
    for (int a = 0; a < 2; ++a)
        #pragma unroll
        for (int b = 0; b < 4; ++b)
            #pragma unroll
            for (int c = 0; c < 4; ++c) acc[a][b][c] = 0.f;

    const int r  = tid >> 1;
    const int hs = tid & 1;
    const int gn = (m0 + r < NV) ? (m0 + r) : 0;

    auto fill = [&](int st, int gi, int k) {
        const __half* srcA = g_y + (size_t)gi * CC + hs * 32;
        uint32_t abase = sb + st * STAGE_BYTES;
        #pragma unroll
        for (int j = 0; j < 4; ++j) {
            uint32_t boff = (uint32_t)(r * 128 + (hs * 4 + j) * 16);
            cp16(abase + SW(boff), srcA + j * 8);
        }
        const __half* srcB = Wh + k * 4096;
        uint32_t bbase = abase + A_BYTES;
        cp16(bbase + tid * 16,        srcB + tid * 8);
        cp16(bbase + (tid + NT) * 16, srcB + (tid + NT) * 8);
    };

    {
        int i0 = ld_idx(nbr, is64, gn, 0);
        int i1 = ld_idx(nbr, is64, gn, 1);
        fill(0, i0, 0);
        asm volatile("cp.async.commit_group;\n");
        fill(1, i1, 1);
        asm volatile("cp.async.commit_group;\n");
    }
    int gi_next = ld_idx(nbr, is64, gn, 2);

    for (int k = 0; k < KK; ++k) {
        const int st = k & 1;
        if (k + 1 < KK)
            asm volatile("cp.async.wait_group 1;\n");
        else
            asm volatile("cp.async.wait_group 0;\n");
        __syncthreads();

        const uint32_t abase = sb + st * STAGE_BYTES;
        const uint32_t bbase = abase + A_BYTES;

        #pragma unroll
        for (int ks = 0; ks < 4; ++ks) {
            const int k0 = ks * 16;
            uint32_t a0[4], a1[4], b0[4], b1[4];
            {
                int row = wm * 32 + (lane & 15);
                int col = k0 + (lane >> 4) * 8;
                uint32_t ad = abase + SW((uint32_t)(row * 128 + col * 2));
                asm volatile("ldmatrix.sync.aligned.m8n8.x4.shared.b16 {%0,%1,%2,%3}, [%4];"
                             : "=r"(a0[0]), "=r"(a0[1]), "=r"(a0[2]), "=r"(a0[3]) : "r"(ad));
                ad = abase + SW((uint32_t)((row + 16) * 128 + col * 2));
                asm volatile("ldmatrix.sync.aligned.m8n8.x4.shared.b16 {%0,%1,%2,%3}, [%4];"
                             : "=r"(a1[0]), "=r"(a1[1]), "=r"(a1[2]), "=r"(a1[3]) : "r"(ad));
            }
            {
                int krow = k0 + ((lane >> 3) & 1) * 8 + (lane & 7);
                int coll = wn * 32 + (lane >> 4) * 8;
                uint32_t ad = bbase + SW((uint32_t)(krow * 128 + coll * 2));
                asm volatile("ldmatrix.sync.aligned.m8n8.x4.trans.shared.b16 {%0,%1,%2,%3}, [%4];"
                             : "=r"(b0[0]), "=r"(b0[1]), "=r"(b0[2]), "=r"(b0[3]) : "r"(ad));
                ad = bbase + SW((uint32_t)(krow * 128 + (coll + 16) * 2));
                asm volatile("ldmatrix.sync.aligned.m8n8.x4.trans.shared.b16 {%0,%1,%2,%3}, [%4];"
                             : "=r"(b1[0]), "=r"(b1[1]), "=r"(b1[2]), "=r"(b1[3]) : "r"(ad));
            }
            #pragma unroll
            for (int mt = 0; mt < 2; ++mt) {
                const uint32_t* A = mt ? a1 : a0;
                #pragma unroll
                for (int nt = 0; nt < 4; ++nt) {
                    const uint32_t* B = (nt < 2) ? b0 : b1;
                    uint32_t bb0 = B[(nt & 1) * 2], bb1 = B[(nt & 1) * 2 + 1];
                    float* C = acc[mt][nt];
                    asm volatile(
                        "mma.sync.aligned.m16n8k16.row.col.f32.f16.f16.f32 "
                        "{%0,%1,%2,%3}, {%4,%5,%6,%7}, {%8,%9}, {%0,%1,%2,%3};"
                        : "+f"(C[0]), "+f"(C[1]), "+f"(C[2]), "+f"(C[3])
                        : "r"(A[0]), "r"(A[1]), "r"(A[2]), "r"(A[3]),
                          "r"(bb0), "r"(bb1));
                }
            }
        }

        if (k + 2 < KK) {
            __syncthreads();
            fill(st, gi_next, k + 2);
            asm volatile("cp.async.commit_group;\n");
            gi_next = ld_idx(nbr, is64, gn, (k + 3 < KK) ? (k + 3) : (KK - 1));
        }
    }

    // ---- epilogue ----
    if (which == 0) {
        float ls[8], lq[8];
        #pragma unroll
        for (int j = 0; j < 8; ++j) { ls[j] = 0.f; lq[j] = 0.f; }

        #pragma unroll
        for (int mt = 0; mt < 2; ++mt) {
            int rbase = m0 + wm * 32 + mt * 16 + (lane >> 2);
            bool v0 = rbase < NV, v1 = rbase + 8 < NV;
            #pragma unroll
            for (int nt = 0; nt < 4; ++nt) {
                int col = wn * 32 + nt * 8 + (lane & 3) * 2;
                float* C = acc[mt][nt];
                if (v0) {
                    size_t o = (size_t)rbase * CC + col;
                    *(__half2*)(g_t16 + o) = __floats2half2_rn(C[0], C[1]);
                    ls[nt * 2]     += C[0]; lq[nt * 2]     += C[0] * C[0];
                    ls[nt * 2 + 1] += C[1]; lq[nt * 2 + 1] += C[1] * C[1];
                }
                if (v1) {
                    size_t o = (size_t)(rbase + 8) * CC + col;
                    *(__half2*)(g_t16 + o) = __floats2half2_rn(C[2], C[3]);
                    ls[nt * 2]     += C[2]; lq[nt * 2]     += C[2] * C[2];
                    ls[nt * 2 + 1] += C[3]; lq[nt * 2 + 1] += C[3] * C[3];
                }
            }
        }
        #pragma unroll
        for (int m = 4; m <= 16; m <<= 1) {
            #pragma unroll
            for (int j = 0; j < 8; ++j) {
                ls[j] += __shfl_xor_sync(0xffffffffu, ls[j], m);
                lq[j] += __shfl_xor_sync(0xffffffffu, lq[j], m);
            }
        }
        float* red = (float*)smem;
        __syncthreads();
        if ((lane >> 2) == 0) {
            #pragma unroll
            for (int j = 0; j < 8; ++j) {
                int cl = (j >> 1) * 8 + (lane & 3) * 2 + (j & 1);
                red[warp * 32 + cl]              = ls[j];
                red[NWARP * 32 + warp * 32 + cl] = lq[j];
            }
        }
        __syncthreads();
        if (tid < 128) {
            int part = tid >> 6, c = tid & 63;
            int cwn = c >> 5, cl = c & 31;
            const float* base = red + part * NWARP * 32;
            float v = 0.f;
            #pragma unroll
            for (int i = 0; i < 4; ++i) v += base[(2 * i + cwn) * 32 + cl];
            atomicAdd(part ? &g_sumsq[1][c] : &g_sum[1][c], v);
        }
    } else {
        #pragma unroll
        for (int mt = 0; mt < 2; ++mt) {
            int rbase = m0 + wm * 32 + mt * 16 + (lane >> 2);
            #pragma unroll
            for (int nt = 0; nt < 4; ++nt) {
                int col = wn * 32 + nt * 8 + (lane & 3) * 2;
                float* C = acc[mt][nt];
                if (rbase < NV) {
                    size_t o = (size_t)rbase * CC + col;
                    float2 rv = *(const float2*)(residual + o);
                    float2 v; v.x = C[0] + rv.x; v.y = C[1] + rv.y;
                    *(float2*)(dout + o) = v;
                }
                if (rbase + 8 < NV) {
                    size_t o = (size_t)(rbase + 8) * CC + col;
                    float2 rv = *(const float2*)(residual + o);
                    float2 v; v.x = C[2] + rv.x; v.y = C[3] + rv.y;
                    *(float2*)(dout + o) = v;
                }
            }
        }
    }
}

// ---------------- launch ----------------
extern "C" void kernel_launch(void* const* d_in, const int* in_sizes, int n_in,
                              void* d_out, int out_size) {
    const float* x      = (const float*)d_in[0];
    const void*  nbr    = d_in[1];
    const float* W1     = (const float*)d_in[2];
    const float* gamma1 = (const float*)d_in[3];
    const float* beta1  = (const float*)d_in[4];
    const float* W2     = (const float*)d_in[5];
    const float* gamma2 = (const float*)d_in[6];
    const float* beta2  = (const float*)d_in[7];
    float* out = (float*)d_out;

    const int conv_grid = (NV + BM - 1) / BM;

    static int attr_set = 0;
    if (!attr_set) {
        cudaFuncSetAttribute(k_conv, cudaFuncAttributeMaxDynamicSharedMemorySize,
                             SMEM_CONV);
        attr_set = 1;
    }

    k_zero<<<1, 64>>>(nbr);                                   // 1
    k_prep<<<PREP_GRID, 256>>>(x, W1, W2, gamma1, beta1);     // 2
    k_conv<<<conv_grid, NT, SMEM_CONV>>>(nbr, 0, nullptr, nullptr); // 3
    k_bnrelu1<<<2048, 256>>>(gamma2, beta2);                  // 4 <- ncu
    k_conv<<<conv_grid, NT, SMEM_CONV>>>(nbr, 1, x, out);     // 5
}